// round 16
// baseline (speedup 1.0000x reference)
#include <cuda_runtime.h>
#include <cuda_bf16.h>
#include <math.h>
#include <stdint.h>

// ---------------- problem constants ----------------
#define TOK   2048          // B*T*HP*WP
#define TWO_D 512
#define DDIM  256
#define KCONV 4608          // 512*9
#define TSTEPS 8
#define PADK3 72            // 64 + 8 bf16 row padding (stage width)

// epilogue flags
#define F_BIAS  1
#define F_ADD   2
#define F_GELU  4
#define F_SCALE 8
#define F_SPLIT 16
#define F_NOC   32
#define F_OUT   64
#define F_ADD2  128

// ---------------- device scratch (no allocs allowed) ----------------
__device__ float g_z   [TOK*TWO_D];
__device__ float g_x   [TOK*TWO_D];
__device__ float g_xe  [TOK*TWO_D];
__device__ float g_xo  [TOK*TWO_D];
__device__ float g_xn  [TOK*TWO_D];
__device__ float g_Bp  [TWO_D*TWO_D];
__device__ float g_xm  [TSTEPS*TWO_D];
__device__ float g_gate[TSTEPS*DDIM];
__device__ float g_src [TSTEPS*TWO_D];
__device__ float g_probs[TOK*4];
__device__ float2 g_hpA[256*256];
__device__ float2 g_hpB[256*256];

// bf16 hi/lo operand buffers
__device__ __nv_bfloat16 g_Ahi[TOK*KCONV];   // big A: col / hid(concat 4096)
__device__ __nv_bfloat16 g_Alo[TOK*KCONV];
__device__ __nv_bfloat16 g_A2hi[TOK*1024];   // small A: zn / x / h / xn / z(dec)
__device__ __nv_bfloat16 g_A2lo[TOK*1024];
__device__ __nv_bfloat16 g_Bhi[512*KCONV];   // B weights (N-major)
__device__ __nv_bfloat16 g_Blo[512*KCONV];

// ---------------- helpers ----------------
__device__ __forceinline__ uint32_t smem_to_u32(const void* smem_ptr) {
    uint32_t addr;
    asm("{ .reg .u64 tmp; cvta.to.shared.u64 tmp, %1; cvt.u32.u64 %0, tmp; }"
        : "=r"(addr) : "l"(smem_ptr));
    return addr;
}
__device__ __forceinline__ float gelu_tanh(float x) {
    float x3 = x * x * x;
    return 0.5f * x * (1.0f + tanhf(0.7978845608028654f * (x + 0.044715f * x3)));
}
__device__ __forceinline__ void ldsm_x4(uint32_t* r, uint32_t addr) {
    asm volatile("ldmatrix.sync.aligned.m8n8.x4.shared.b16 {%0,%1,%2,%3}, [%4];"
        : "=r"(r[0]), "=r"(r[1]), "=r"(r[2]), "=r"(r[3]) : "r"(addr));
}
__device__ __forceinline__ void ldsm_x2(uint32_t* r, uint32_t addr) {
    asm volatile("ldmatrix.sync.aligned.m8n8.x2.shared.b16 {%0,%1}, [%2];"
        : "=r"(r[0]), "=r"(r[1]) : "r"(addr));
}
__device__ __forceinline__ void mma_bf16(float* d, const uint32_t* a, const uint32_t* b) {
    asm volatile(
        "mma.sync.aligned.m16n8k16.row.col.f32.bf16.bf16.f32 "
        "{%0,%1,%2,%3}, {%4,%5,%6,%7}, {%8,%9}, {%0,%1,%2,%3};"
        : "+f"(d[0]), "+f"(d[1]), "+f"(d[2]), "+f"(d[3])
        : "r"(a[0]), "r"(a[1]), "r"(a[2]), "r"(a[3]), "r"(b[0]), "r"(b[1]));
}
__device__ __forceinline__ void cpasync16(uint32_t s, const void* g) {
    asm volatile("cp.async.cg.shared.global [%0], [%1], 16;" :: "r"(s), "l"(g));
}
__device__ __forceinline__ void split1(float v, __nv_bfloat16& h, __nv_bfloat16& l) {
    h = __float2bfloat16(v);
    l = __float2bfloat16(v - __bfloat162float(h));
}

// stage layout constants (bytes): 64-row tiles, k-stage 64, 2 pipeline stages
#define MAT_B   (64 * PADK3 * 2)        // 9216
#define STAGE_B (4 * MAT_B)             // 36864
#define NSTAGE  2
#define TG_SMEM (NSTAGE * STAGE_B)      // 73728

// ================= tensor-core GEMM (bf16x3, k64, 2-stage cp.async) ========
// C[M,N] = fp32(A) @ fp32(B); A ≈ Ahi+Alo row-major [M][K]; B N-major [N][K].
// Ns = row stride for F_SPLIT output. Batched over blockIdx.z.
__global__ __launch_bounds__(128, 3)
void tgemm(const __nv_bfloat16* __restrict__ Ahi, const __nv_bfloat16* __restrict__ Alo,
           const __nv_bfloat16* __restrict__ Bhi, const __nv_bfloat16* __restrict__ Blo,
           float* __restrict__ C,
           __nv_bfloat16* __restrict__ Chi, __nv_bfloat16* __restrict__ Clo,
           int M, int N, int K, int Ns,
           const float* __restrict__ bias,
           const float* __restrict__ add_src,
           const float* __restrict__ add2,
           const float* __restrict__ probs,
           int flags, long sA, long sB, long sC, long sCh)
{
    extern __shared__ __align__(16) char dsmem[];
    const uint32_t ub = smem_to_u32(dsmem);

    const int tid = threadIdx.x;
    const int wid = tid >> 5;
    const int lane = tid & 31;
    const int warp_m = wid >> 1;
    const int warp_n = wid & 1;

    const int z = blockIdx.z;
    const __nv_bfloat16* Ah = Ahi + (size_t)z * sA;
    const __nv_bfloat16* Al = Alo + (size_t)z * sA;
    const __nv_bfloat16* Bh = Bhi + (size_t)z * sB;
    const __nv_bfloat16* Bl = Blo + (size_t)z * sB;
    const int bm = blockIdx.y * 64;
    const int bn = blockIdx.x * 64;

    float acc[2][4][4];
    #pragma unroll
    for (int i = 0; i < 2; i++)
        #pragma unroll
        for (int j = 0; j < 4; j++)
            #pragma unroll
            for (int q = 0; q < 4; q++) acc[i][j][q] = 0.0f;

    const int c0row = tid >> 3;
    const int c0kc  = (tid & 7) * 8;

    const uint32_t aoff = (uint32_t)((warp_m * 32 + (lane & 15)) * PADK3 + (lane >> 4) * 8) * 2;
    const uint32_t boff = (uint32_t)((warp_n * 32 + (lane & 7)) * PADK3 + ((lane >> 3) & 1) * 8) * 2;

    const int NKS = K >> 6;

    {
        const uint32_t sb = ub;
        #pragma unroll
        for (int it = 0; it < 4; it++) {
            const int row = c0row + it * 16;
            const uint32_t so = (uint32_t)(row * PADK3 + c0kc) * 2;
            const size_t ga = (size_t)(bm + row) * K + c0kc;
            const size_t gb = (size_t)(bn + row) * K + c0kc;
            cpasync16(sb + so, Ah + ga);
            cpasync16(sb + MAT_B + so, Al + ga);
            cpasync16(sb + 2 * MAT_B + so, Bh + gb);
            cpasync16(sb + 3 * MAT_B + so, Bl + gb);
        }
        asm volatile("cp.async.commit_group;");
    }

    for (int i = 0; i < NKS; i++) {
        asm volatile("cp.async.wait_group 0;");
        __syncthreads();

        if (i + 1 < NKS) {
            const uint32_t sb = ub + ((i + 1) & 1) * STAGE_B;
            const int k0 = (i + 1) << 6;
            #pragma unroll
            for (int it = 0; it < 4; it++) {
                const int row = c0row + it * 16;
                const uint32_t so = (uint32_t)(row * PADK3 + c0kc) * 2;
                const size_t ga = (size_t)(bm + row) * K + k0 + c0kc;
                const size_t gb = (size_t)(bn + row) * K + k0 + c0kc;
                cpasync16(sb + so, Ah + ga);
                cpasync16(sb + MAT_B + so, Al + ga);
                cpasync16(sb + 2 * MAT_B + so, Bh + gb);
                cpasync16(sb + 3 * MAT_B + so, Bl + gb);
            }
        }
        asm volatile("cp.async.commit_group;");

        const uint32_t sb = ub + (i & 1) * STAGE_B;
        #pragma unroll
        for (int ks = 0; ks < 4; ks++) {
            const uint32_t kb = (uint32_t)ks * 32;
            uint32_t ah[2][4], al[2][4];
            uint32_t bh[4][2], bl[4][2];
            #pragma unroll
            for (int mi = 0; mi < 2; mi++) {
                const uint32_t ao = sb + aoff + (uint32_t)(mi * 16 * PADK3) * 2 + kb;
                ldsm_x4(ah[mi], ao);
                ldsm_x4(al[mi], ao + MAT_B);
            }
            #pragma unroll
            for (int nj = 0; nj < 4; nj++) {
                const uint32_t bo = sb + 2 * MAT_B + boff + (uint32_t)(nj * 8 * PADK3) * 2 + kb;
                ldsm_x2(bh[nj], bo);
                ldsm_x2(bl[nj], bo + MAT_B);
            }
            #pragma unroll
            for (int nj = 0; nj < 4; nj++)
                #pragma unroll
                for (int mi = 0; mi < 2; mi++)
                    mma_bf16(acc[mi][nj], ah[mi], bh[nj]);
            #pragma unroll
            for (int nj = 0; nj < 4; nj++)
                #pragma unroll
                for (int mi = 0; mi < 2; mi++)
                    mma_bf16(acc[mi][nj], ah[mi], bl[nj]);
            #pragma unroll
            for (int nj = 0; nj < 4; nj++)
                #pragma unroll
                for (int mi = 0; mi < 2; mi++)
                    mma_bf16(acc[mi][nj], al[mi], bh[nj]);
        }
    }

    // epilogue
    float* Cp = C + (size_t)z * sC;
    __nv_bfloat16* Chp = Chi + (size_t)z * sCh;
    __nv_bfloat16* Clp = Clo + (size_t)z * sCh;
    #pragma unroll
    for (int mi = 0; mi < 2; mi++) {
        #pragma unroll
        for (int nj = 0; nj < 4; nj++) {
            const int m0 = bm + warp_m * 32 + mi * 16 + (lane >> 2);
            const int n0 = bn + warp_n * 32 + nj * 8 + (lane & 3) * 2;
            float v00 = acc[mi][nj][0], v01 = acc[mi][nj][1];
            float v10 = acc[mi][nj][2], v11 = acc[mi][nj][3];
            if (flags & F_BIAS) {
                const float2 bb = *(const float2*)&bias[n0];
                v00 += bb.x; v01 += bb.y; v10 += bb.x; v11 += bb.y;
            }
            if (flags & F_ADD) {
                const float2 r0 = *(const float2*)&add_src[(size_t)m0 * N + n0];
                const float2 r1 = *(const float2*)&add_src[(size_t)(m0 + 8) * N + n0];
                v00 += r0.x; v01 += r0.y; v10 += r1.x; v11 += r1.y;
            }
            if (flags & F_ADD2) {
                const float2 r0 = *(const float2*)&add2[(size_t)m0 * N + n0];
                const float2 r1 = *(const float2*)&add2[(size_t)(m0 + 8) * N + n0];
                v00 += r0.x; v01 += r0.y; v10 += r1.x; v11 += r1.y;
            }
            if (flags & F_GELU) {
                v00 = gelu_tanh(v00); v01 = gelu_tanh(v01);
                v10 = gelu_tanh(v10); v11 = gelu_tanh(v11);
            }
            if (flags & F_SCALE) {
                const float s0 = probs[(size_t)m0 * 4 + z];
                const float s1 = probs[(size_t)(m0 + 8) * 4 + z];
                v00 *= s0; v01 *= s0; v10 *= s1; v11 *= s1;
            }
            if (flags & F_OUT) {
                #pragma unroll
                for (int rr = 0; rr < 2; rr++) {
                    const int m = m0 + rr * 8;
                    const int t = m >> 8, hp = (m >> 4) & 15, wp = m & 15;
                    const int c = n0 >> 8, py = (n0 >> 4) & 15, px = n0 & 15;
                    const size_t oi = (((size_t)(t * 4 + c) * 256) + hp * 16 + py) * 256
                                      + wp * 16 + px;
                    float2 o; o.x = (rr ? v10 : v00); o.y = (rr ? v11 : v01);
                    *(float2*)&Cp[oi] = o;
                }
            } else if (!(flags & F_NOC)) {
                float2 o0; o0.x = v00; o0.y = v01;
                float2 o1; o1.x = v10; o1.y = v11;
                *(float2*)&Cp[(size_t)m0 * N + n0] = o0;
                *(float2*)&Cp[(size_t)(m0 + 8) * N + n0] = o1;
            }
            if (flags & F_SPLIT) {
                __nv_bfloat16 h0, l0, h1, l1, h2, l2, h3, l3;
                split1(v00, h0, l0); split1(v01, h1, l1);
                split1(v10, h2, l2); split1(v11, h3, l3);
                *(__nv_bfloat162*)&Chp[(size_t)m0 * Ns + n0] = __halves2bfloat162(h0, h1);
                *(__nv_bfloat162*)&Clp[(size_t)m0 * Ns + n0] = __halves2bfloat162(l0, l1);
                *(__nv_bfloat162*)&Chp[(size_t)(m0 + 8) * Ns + n0] = __halves2bfloat162(h2, h3);
                *(__nv_bfloat162*)&Clp[(size_t)(m0 + 8) * Ns + n0] = __halves2bfloat162(l2, l3);
            }
        }
    }
}

// ================= producers emitting bf16 hi/lo directly =================
__global__ void patchify_split(const float* __restrict__ x,
                               __nv_bfloat16* __restrict__ hi,
                               __nv_bfloat16* __restrict__ lo)
{
    int idx = blockIdx.x * blockDim.x + threadIdx.x;
    if (idx >= TOK * 1024) return;
    int tok = idx >> 10, k = idx & 1023;
    int t = tok >> 8, hp = (tok >> 4) & 15, wp = tok & 15;
    int c = k >> 8, py = (k >> 4) & 15, px = k & 15;
    float v = x[(((size_t)(t * 4 + c) * 256) + hp * 16 + py) * 256 + wp * 16 + px];
    split1(v, hi[idx], lo[idx]);
}

__global__ void ln_split(const float* __restrict__ X, float* __restrict__ Yf,
                         __nv_bfloat16* __restrict__ Yh, __nv_bfloat16* __restrict__ Yl,
                         const float* __restrict__ w, const float* __restrict__ b)
{
    __shared__ float sh[256];
    int tok = blockIdx.x, tid = threadIdx.x;
    const float* x = X + (size_t)tok * 512;
    float v1 = x[tid], v2 = x[tid + 256];
    sh[tid] = v1 + v2;
    __syncthreads();
    for (int s = 128; s > 0; s >>= 1) { if (tid < s) sh[tid] += sh[tid + s]; __syncthreads(); }
    float mean = sh[0] * (1.0f / 512.0f);
    __syncthreads();
    float d1 = v1 - mean, d2 = v2 - mean;
    sh[tid] = d1 * d1 + d2 * d2;
    __syncthreads();
    for (int s = 128; s > 0; s >>= 1) { if (tid < s) sh[tid] += sh[tid + s]; __syncthreads(); }
    float rstd = rsqrtf(sh[0] * (1.0f / 512.0f) + 1e-5f);
    float y1 = d1 * rstd * w[tid] + b[tid];
    float y2 = d2 * rstd * w[tid + 256] + b[tid + 256];
    size_t o1 = (size_t)tok * 512 + tid, o2 = o1 + 256;
    if (Yf) { Yf[o1] = y1; Yf[o2] = y2; }
    split1(y1, Yh[o1], Yl[o1]);
    split1(y2, Yh[o2], Yl[o2]);
}

__global__ void im2col_bf16(const __nv_bfloat16* __restrict__ znh,
                            const __nv_bfloat16* __restrict__ znl,
                            __nv_bfloat16* __restrict__ colh,
                            __nv_bfloat16* __restrict__ coll)
{
    int bid = blockIdx.x;
    int tok = bid / 9, pos = bid - tok * 9;
    int t = tok >> 8, hw = tok & 255;
    int y = hw >> 4, x = hw & 15;
    int ny = y + pos / 3 - 1, nx = x + pos % 3 - 1;
    int i = threadIdx.x;  // 0..63, each 8 bf16 (16B)
    uint4* dh = (uint4*)(colh + (size_t)tok * KCONV + pos * 512);
    uint4* dl = (uint4*)(coll + (size_t)tok * KCONV + pos * 512);
    if ((unsigned)ny < 16u && (unsigned)nx < 16u) {
        const size_t src = (size_t)(t * 256 + ny * 16 + nx) * 512;
        dh[i] = ((const uint4*)(znh + src))[i];
        dl[i] = ((const uint4*)(znl + src))[i];
    } else {
        uint4 zr = make_uint4(0, 0, 0, 0);
        dh[i] = zr;
        dl[i] = zr;
    }
}

// tiled transpose+split: out[z*sDst + n*Kld + k] = src[z*sSrc + k*N + n]
// grid (K/32, N/32, z), block (32, 8)
__global__ void tsplit_kernel(const float* __restrict__ src,
                              __nv_bfloat16* __restrict__ hi,
                              __nv_bfloat16* __restrict__ lo,
                              int K, int N, int Kld, long sSrc, long sDst)
{
    __shared__ float tile[32][33];
    const int kb = blockIdx.x * 32, nb = blockIdx.y * 32;
    const int z = blockIdx.z;
    const int tx = threadIdx.x, ty = threadIdx.y;
    const float* s = src + (size_t)z * sSrc;
    #pragma unroll
    for (int i = ty; i < 32; i += 8)
        tile[i][tx] = s[(size_t)(kb + i) * N + nb + tx];
    __syncthreads();
    __nv_bfloat16* hp = hi + (size_t)z * sDst;
    __nv_bfloat16* lp = lo + (size_t)z * sDst;
    #pragma unroll
    for (int i = ty; i < 32; i += 8) {
        const float v = tile[tx][i];
        __nv_bfloat16 h, l;
        split1(v, h, l);
        const size_t o = (size_t)(nb + i) * Kld + kb + tx;
        hp[o] = h;
        lp[o] = l;
    }
}

// tiled pack complex -> Bt[n][k] of 512x512 block matrix, split.
__global__ void pack_cplx_bt(const float* __restrict__ Re, const float* __restrict__ Im,
                             __nv_bfloat16* __restrict__ hi, __nv_bfloat16* __restrict__ lo)
{
    __shared__ float tile[32][33];
    const int kb = blockIdx.x * 32, nb = blockIdx.y * 32;
    const int tx = threadIdx.x, ty = threadIdx.y;
    const bool khi = kb >= 256, nhi = nb >= 256;
    const float* srcq = khi ? (nhi ? Re : Im) : (nhi ? Im : Re);
    const float sgn = (khi && !nhi) ? -1.0f : 1.0f;
    const int kq = kb - (khi ? 256 : 0), nq = nb - (nhi ? 256 : 0);
    #pragma unroll
    for (int i = ty; i < 32; i += 8)
        tile[i][tx] = sgn * srcq[(size_t)(kq + i) * 256 + nq + tx];
    __syncthreads();
    #pragma unroll
    for (int i = ty; i < 32; i += 8) {
        const float v = tile[tx][i];
        __nv_bfloat16 h, l;
        split1(v, h, l);
        const size_t o = (size_t)(nb + i) * 512 + kb + tx;
        hi[o] = h;
        lo[o] = l;
    }
}

// staged conv-weight pack: one CTA per oc
__global__ void conv_w_tsplit(const float* __restrict__ cw,
                              __nv_bfloat16* __restrict__ hi, __nv_bfloat16* __restrict__ lo)
{
    __shared__ __nv_bfloat16 sh[KCONV];
    __shared__ __nv_bfloat16 sl[KCONV];
    const int oc = blockIdx.x;
    const int tid = threadIdx.x;
    const float* s = cw + (size_t)oc * KCONV;
    for (int i = tid; i < KCONV; i += 256) {
        const int ic = i / 9, pos = i - ic * 9;
        __nv_bfloat16 h, l;
        split1(s[i], h, l);
        sh[pos * 512 + ic] = h;
        sl[pos * 512 + ic] = l;
    }
    __syncthreads();
    __nv_bfloat16* hp = hi + (size_t)oc * KCONV;
    __nv_bfloat16* lp = lo + (size_t)oc * KCONV;
    for (int i = tid; i < KCONV; i += 256) {
        hp[i] = sh[i];
        lp[i] = sl[i];
    }
}

// ================= elementwise / small kernels =================
__global__ void small_mm(const float* __restrict__ A, const float* __restrict__ B,
                         float* __restrict__ C, int M, int N, int K,
                         const float* __restrict__ bias, int act)
{
    int n = blockIdx.x * blockDim.x + threadIdx.x;
    int m = blockIdx.y;
    if (n >= N || m >= M) return;
    float acc = 0.0f;
    for (int k = 0; k < K; k++) acc += A[m * K + k] * B[k * N + n];
    if (bias) acc += bias[n];
    if (act == 1) acc = 1.0f / (1.0f + expf(-acc));
    C[m * N + n] = acc;
}

__global__ void pack_cplx_kernel(const float* __restrict__ Re, const float* __restrict__ Im,
                                 float* __restrict__ Bp)
{
    int idx = blockIdx.x * blockDim.x + threadIdx.x;
    if (idx >= 512 * 512) return;
    int k = idx >> 9, n = idx & 511;
    float v;
    if (k < 256) v = (n < 256) ? Re[k * 256 + n] : Im[k * 256 + (n - 256)];
    else {
        int d = k - 256;
        v = (n < 256) ? -Im[d * 256 + n] : Re[d * 256 + (n - 256)];
    }
    Bp[idx] = v;
}

__global__ void mean_kernel(const float* __restrict__ xe, float* __restrict__ xm)
{
    int t = blockIdx.x, c = threadIdx.x;
    float s = 0.0f;
    for (int hw = 0; hw < 256; hw++) s += xe[(size_t)((t << 8) + hw) * 512 + c];
    xm[t * 512 + c] = s * (1.0f / 256.0f);
}

__global__ void scan_kernel(const float* __restrict__ xe, const float* __restrict__ gate,
                            const float* __restrict__ src,
                            const float* __restrict__ lam_re, const float* __restrict__ lam_im,
                            const float* __restrict__ dt,
                            const float2* __restrict__ hprev,
                            __nv_bfloat16* __restrict__ hh, __nv_bfloat16* __restrict__ hl,
                            float2* __restrict__ lasth)
{
    int e = threadIdx.x;
    int hw = blockIdx.x;
    float lr = lam_re[e], li = lam_im[e];
    float lamr = -(log1pf(expf(lr)) + 0.01f);
    float lami = li;
    float il2 = 1.0f / (lamr * lamr + lami * lami);
    float2 hp = hprev[hw * 256 + e];
    float hr = 0.0f, hi = 0.0f;
    float outr = 0.0f, outi = 0.0f;
    #pragma unroll
    for (int t = 0; t < TSTEPS; t++) {
        float d = dt[t];
        float ed = expf(lamr * d);
        float dr = ed * cosf(lami * d), di = ed * sinf(lami * d);
        float nr = dr - 1.0f;
        float ofr = (nr * lamr + di * lami) * il2;
        float ofi = (di * lamr - nr * lami) * il2;
        int tok = t * 256 + hw;
        float xr = xe[(size_t)tok * 512 + e], xi = xe[(size_t)tok * 512 + 256 + e];
        float g = gate[t * 256 + e];
        float sr = src[t * 512 + e], si = src[t * 512 + 256 + e];
        float fr = xr * g + sr * (1.0f - g);
        float fi = xi * g + si * (1.0f - g);
        float ur = fr * ofr - fi * ofi;
        float ui = fr * ofi + fi * ofr;
        float nhr = dr * hr - di * hi + ur;
        float nhi = dr * hi + di * hr + ui;
        hr = nhr; hi = nhi;
        outr = hr + (hp.x * dr - hp.y * di);
        outi = hi + (hp.x * di + hp.y * dr);
        size_t o1 = (size_t)tok * 512 + e, o2 = o1 + 256;
        split1(outr, hh[o1], hl[o1]);
        split1(outi, hh[o2], hl[o2]);
    }
    lasth[hw * 256 + e] = make_float2(outr, outi);
}

__global__ void probs_kernel(const float* __restrict__ xn, const float* __restrict__ Wr,
                             float* __restrict__ probs)
{
    int gwarp = (blockIdx.x * blockDim.x + threadIdx.x) >> 5;
    int lane = threadIdx.x & 31;
    if (gwarp >= TOK) return;
    const float* x = xn + (size_t)gwarp * 512;
    float l0 = 0, l1 = 0, l2 = 0, l3 = 0;
    for (int k = lane; k < 512; k += 32) {
        float xv = x[k];
        const float* wr = Wr + k * 4;
        l0 += xv * wr[0]; l1 += xv * wr[1]; l2 += xv * wr[2]; l3 += xv * wr[3];
    }
    #pragma unroll
    for (int off = 16; off > 0; off >>= 1) {
        l0 += __shfl_xor_sync(0xffffffffu, l0, off);
        l1 += __shfl_xor_sync(0xffffffffu, l1, off);
        l2 += __shfl_xor_sync(0xffffffffu, l2, off);
        l3 += __shfl_xor_sync(0xffffffffu, l3, off);
    }
    if (lane == 0) {
        float mx = fmaxf(fmaxf(l0, l1), fmaxf(l2, l3));
        float e0 = expf(l0 - mx), e1 = expf(l1 - mx), e2 = expf(l2 - mx), e3 = expf(l3 - mx);
        float inv = 1.0f / (e0 + e1 + e2 + e3);
        probs[gwarp * 4 + 0] = e0 * inv;
        probs[gwarp * 4 + 1] = e1 * inv;
        probs[gwarp * 4 + 2] = e2 * inv;
        probs[gwarp * 4 + 3] = e3 * inv;
    }
}

__global__ void zero_f2_kernel(float2* p, int n)
{
    int i = blockIdx.x * blockDim.x + threadIdx.x;
    if (i < n) p[i] = make_float2(0.f, 0.f);
}

// ---------------- host orchestration ----------------
template <typename T, size_t N>
static T* sym_addr(const T (&sym)[N]) {
    void* p = nullptr;
    cudaGetSymbolAddress(&p, (const void*)&sym);
    return (T*)p;
}

extern "C" void kernel_launch(void* const* d_in, const int* in_sizes, int n_in,
                              void* d_out, int out_size)
{
    const float* x      = (const float*)d_in[0];
    const float* dt     = (const float*)d_in[1];
    const float* Wenc   = (const float*)d_in[2];
    const float* benc   = (const float*)d_in[3];
    const float* Wdec   = (const float*)d_in[4];
    const float* bdec   = (const float*)d_in[5];
    const float* ln_sp_w= (const float*)d_in[6];
    const float* ln_sp_b= (const float*)d_in[7];
    const float* conv_w = (const float*)d_in[8];
    const float* conv_b = (const float*)d_in[9];
    const float* E_re   = (const float*)d_in[10];
    const float* E_im   = (const float*)d_in[11];
    const float* Ed_re  = (const float*)d_in[12];
    const float* Ed_im  = (const float*)d_in[13];
    const float* Ws_re  = (const float*)d_in[14];
    const float* Ws_im  = (const float*)d_in[15];
    const float* Wg     = (const float*)d_in[16];
    const float* bg     = (const float*)d_in[17];
    const float* lam_re = (const float*)d_in[18];
    const float* lam_im = (const float*)d_in[19];
    const float* ln_t_w = (const float*)d_in[20];
    const float* ln_t_b = (const float*)d_in[21];
    const float* Wr     = (const float*)d_in[22];
    const float* W1     = (const float*)d_in[23];
    const float* W2     = (const float*)d_in[24];

    float*  p_z    = sym_addr(g_z);
    float*  p_x    = sym_addr(g_x);
    float*  p_xe   = sym_addr(g_xe);
    float*  p_xo   = sym_addr(g_xo);
    float*  p_xn   = sym_addr(g_xn);
    float*  p_Bp   = sym_addr(g_Bp);
    float*  p_xm   = sym_addr(g_xm);
    float*  p_gate = sym_addr(g_gate);
    float*  p_src  = sym_addr(g_src);
    float*  p_probs= sym_addr(g_probs);
    float2* p_hpA  = sym_addr(g_hpA);
    float2* p_hpB  = sym_addr(g_hpB);
    __nv_bfloat16* p_Ahi  = sym_addr(g_Ahi);
    __nv_bfloat16* p_Alo  = sym_addr(g_Alo);
    __nv_bfloat16* p_A2hi = sym_addr(g_A2hi);
    __nv_bfloat16* p_A2lo = sym_addr(g_A2lo);
    __nv_bfloat16* p_Bhi  = sym_addr(g_Bhi);
    __nv_bfloat16* p_Blo  = sym_addr(g_Blo);

    cudaFuncSetAttribute(tgemm, cudaFuncAttributeMaxDynamicSharedMemorySize, TG_SMEM);

    // zero h_prev for layer 0
    zero_f2_kernel<<<256, 256>>>(p_hpA, 256 * 256);

    // ---------------- encoder ----------------
    patchify_split<<<(TOK * 1024) / 256, 256>>>(x, p_Ahi, p_Alo);
    tsplit_kernel<<<dim3(1024 / 32, 512 / 32, 1), dim3(32, 8)>>>(
        Wenc, p_Bhi, p_Blo, 1024, 512, 1024, 0, 0);
    tgemm<<<dim3(8, 32, 1), 128, TG_SMEM>>>(p_Ahi, p_Alo, p_Bhi, p_Blo, p_z,
                                            p_A2hi, p_A2lo, TOK, 512, 1024, 512,
                                            benc, nullptr, nullptr, nullptr,
                                            F_BIAS, 0, 0, 0, 0);

    for (int l = 0; l < 2; l++) {
        const float* cE_re  = E_re  + l * 65536;
        const float* cE_im  = E_im  + l * 65536;
        const float* cEd_re = Ed_re + l * 65536;
        const float* cEd_im = Ed_im + l * 65536;
        const float* cWs_re = Ws_re + l * 65536;
        const float* cWs_im = Ws_im + l * 65536;

        // spatial LN -> zn hi/lo only
        ln_split<<<TOK, 256>>>(p_z, nullptr, p_A2hi, p_A2lo,
                               ln_sp_w + l * 512, ln_sp_b + l * 512);

        // conv: bf16 im2col + GEMM, epilogue = bias + residual, fp32 x + hi/lo x
        im2col_bf16<<<TOK * 9, 64>>>(p_A2hi, p_A2lo, p_Ahi, p_Alo);
        conv_w_tsplit<<<512, 256>>>(conv_w + (size_t)l * 512 * 512 * 9, p_Bhi, p_Blo);
        tgemm<<<dim3(8, 32, 1), 128, TG_SMEM>>>(p_Ahi, p_Alo, p_Bhi, p_Blo, p_x,
                                                p_A2hi, p_A2lo, TOK, 512, KCONV, 512,
                                                conv_b + l * 512, p_z, nullptr, nullptr,
                                                F_BIAS | F_ADD | F_SPLIT, 0, 0, 0, 0);

        // x_eigen = x @ E
        pack_cplx_bt<<<dim3(16, 16), dim3(32, 8)>>>(cE_re, cE_im, p_Bhi, p_Blo);
        tgemm<<<dim3(8, 32, 1), 128, TG_SMEM>>>(p_A2hi, p_A2lo, p_Bhi, p_Blo, p_xe,
                                                nullptr, nullptr, TOK, 512, 512, 512,
                                                nullptr, nullptr, nullptr, nullptr,
                                                0, 0, 0, 0, 0);

        // spatial mean -> xm (8 x 512)
        mean_kernel<<<8, 512>>>(p_xe, p_xm);

        // source_seq = xm @ Ws, gate_seq = sigmoid(xm @ Wg + bg)  (tiny, fp32)
        pack_cplx_kernel<<<1024, 256>>>(cWs_re, cWs_im, p_Bp);
        small_mm<<<dim3(4, 8), 128>>>(p_xm, p_Bp, p_src, 8, 512, 512, nullptr, 0);
        small_mm<<<dim3(2, 8), 128>>>(p_xm, Wg + l * 512 * 256, p_gate, 8, 256, 512,
                                      bg + l * 256, 1);

        // temporal scan -> h hi/lo (GEMM A operand)
        float2* hp_in  = (l == 0) ? p_hpA : p_hpB;
        float2* hp_out = (l == 0) ? p_hpB : p_hpA;
        scan_kernel<<<256, 256>>>(p_xe, p_gate, p_src, lam_re + l * 256, lam_im + l * 256,
                                  dt, hp_in, p_A2hi, p_A2lo, hp_out);

        // x_out = h @ Ed
        pack_cplx_bt<<<dim3(16, 16), dim3(32, 8)>>>(cEd_re, cEd_im, p_Bhi, p_Blo);
        tgemm<<<dim3(8, 32, 1), 128, TG_SMEM>>>(p_A2hi, p_A2lo, p_Bhi, p_Blo, p_xo,
                                                nullptr, nullptr, TOK, 512, 512, 512,
                                                nullptr, nullptr, nullptr, nullptr,
                                                0, 0, 0, 0, 0);

        // temporal LN -> xn fp32 + hi/lo
        ln_split<<<TOK, 256>>>(p_xo, p_xn, p_A2hi, p_A2lo,
                               ln_t_w + l * 512, ln_t_b + l * 512);

        // router probs (fp32 xn)
        probs_kernel<<<TOK / 8, 256>>>(p_xn, Wr + l * 512 * 4, p_probs);

        // MoE W1: hid_cat[tok][e*1024+f] = probs[tok,e] * gelu(xn @ W1[e])
        tsplit_kernel<<<dim3(512 / 32, 1024 / 32, 4), dim3(32, 8)>>>(
            W1 + (size_t)l * 4 * 512 * 1024, p_Bhi, p_Blo, 512, 1024, 512,
            (long)512 * 1024, (long)512 * 1024);
        tgemm<<<dim3(16, 32, 4), 128, TG_SMEM>>>(p_A2hi, p_A2lo, p_Bhi, p_Blo, nullptr,
                                                 p_Ahi, p_Alo, TOK, 1024, 512, 4096,
                                                 nullptr, nullptr, nullptr, p_probs,
                                                 F_GELU | F_SCALE | F_SPLIT | F_NOC,
                                                 0, (long)512 * 1024, 0, 1024);

        // MoE W2 (concat-K): z = x + xn + hid_cat @ W2_cat; l=1 also emits z hi/lo
        tsplit_kernel<<<dim3(1024 / 32, 512 / 32, 4), dim3(32, 8)>>>(
            W2 + (size_t)l * 4 * 1024 * 512, p_Bhi, p_Blo, 1024, 512, 4096,
            (long)1024 * 512, 1024);
        tgemm<<<dim3(8, 32, 1), 128, TG_SMEM>>>(p_Ahi, p_Alo, p_Bhi, p_Blo, p_z,
                                                p_A2hi, p_A2lo, TOK, 512, 4096, 512,
                                                nullptr, p_x, p_xn, nullptr,
                                                F_ADD | F_ADD2 | (l == 1 ? F_SPLIT : 0),
                                                0, 0, 0, 0);
    }

    // ---------------- decoder (fused unpatchify; z hi/lo from W2 epilogue) --
    tsplit_kernel<<<dim3(512 / 32, 1024 / 32, 1), dim3(32, 8)>>>(
        Wdec, p_Bhi, p_Blo, 512, 1024, 512, 0, 0);
    tgemm<<<dim3(16, 32, 1), 128, TG_SMEM>>>(p_A2hi, p_A2lo, p_Bhi, p_Blo, (float*)d_out,
                                             nullptr, nullptr, TOK, 1024, 512, 1024,
                                             bdec, nullptr, nullptr, nullptr,
                                             F_BIAS | F_OUT, 0, 0, 0, 0);
}

// round 17
// speedup vs baseline: 1.0563x; 1.0563x over previous
#include <cuda_runtime.h>
#include <cuda_bf16.h>
#include <math.h>
#include <stdint.h>

// ---------------- problem constants ----------------
#define TOK   2048          // B*T*HP*WP
#define TWO_D 512
#define DDIM  256
#define KCONV 4608          // 512*9
#define TSTEPS 8
#define PADK3 72            // 64 + 8 bf16 row padding (stage width)

// epilogue flags
#define F_BIAS  1
#define F_ADD   2
#define F_GELU  4
#define F_SCALE 8
#define F_SPLIT 16
#define F_NOC   32
#define F_OUT   64

// ---------------- device scratch (no allocs allowed) ----------------
__device__ float g_z   [TOK*TWO_D];
__device__ float g_x   [TOK*TWO_D];
__device__ float g_xe  [TOK*TWO_D];
__device__ float g_xo  [TOK*TWO_D];
__device__ float g_xn  [TOK*TWO_D];
__device__ float g_oexp[4*TOK*TWO_D];
__device__ float g_Bp  [TWO_D*TWO_D];
__device__ float g_xm  [TSTEPS*TWO_D];
__device__ float g_mpart[TSTEPS*8*TWO_D];
__device__ float g_gate[TSTEPS*DDIM];
__device__ float g_src [TSTEPS*TWO_D];
__device__ float g_probs[TOK*4];
__device__ float2 g_hpA[256*256];
__device__ float2 g_hpB[256*256];

// bf16 hi/lo operand buffers
__device__ __nv_bfloat16 g_Ahi[TOK*KCONV];   // big A: col / hid
__device__ __nv_bfloat16 g_Alo[TOK*KCONV];
__device__ __nv_bfloat16 g_A2hi[TOK*1024];   // small A: zn / x / h / xn / z(dec)
__device__ __nv_bfloat16 g_A2lo[TOK*1024];
__device__ __nv_bfloat16 g_Bhi[512*KCONV];   // B weights (N-major)
__device__ __nv_bfloat16 g_Blo[512*KCONV];

// ---------------- helpers ----------------
__device__ __forceinline__ uint32_t smem_to_u32(const void* smem_ptr) {
    uint32_t addr;
    asm("{ .reg .u64 tmp; cvta.to.shared.u64 tmp, %1; cvt.u32.u64 %0, tmp; }"
        : "=r"(addr) : "l"(smem_ptr));
    return addr;
}
__device__ __forceinline__ float gelu_tanh(float x) {
    float x3 = x * x * x;
    return 0.5f * x * (1.0f + tanhf(0.7978845608028654f * (x + 0.044715f * x3)));
}
__device__ __forceinline__ void ldsm_x4(uint32_t* r, uint32_t addr) {
    asm volatile("ldmatrix.sync.aligned.m8n8.x4.shared.b16 {%0,%1,%2,%3}, [%4];"
        : "=r"(r[0]), "=r"(r[1]), "=r"(r[2]), "=r"(r[3]) : "r"(addr));
}
__device__ __forceinline__ void ldsm_x2(uint32_t* r, uint32_t addr) {
    asm volatile("ldmatrix.sync.aligned.m8n8.x2.shared.b16 {%0,%1}, [%2];"
        : "=r"(r[0]), "=r"(r[1]) : "r"(addr));
}
__device__ __forceinline__ void mma_bf16(float* d, const uint32_t* a, const uint32_t* b) {
    asm volatile(
        "mma.sync.aligned.m16n8k16.row.col.f32.bf16.bf16.f32 "
        "{%0,%1,%2,%3}, {%4,%5,%6,%7}, {%8,%9}, {%0,%1,%2,%3};"
        : "+f"(d[0]), "+f"(d[1]), "+f"(d[2]), "+f"(d[3])
        : "r"(a[0]), "r"(a[1]), "r"(a[2]), "r"(a[3]), "r"(b[0]), "r"(b[1]));
}
__device__ __forceinline__ void cpasync16(uint32_t s, const void* g) {
    asm volatile("cp.async.cg.shared.global [%0], [%1], 16;" :: "r"(s), "l"(g));
}
__device__ __forceinline__ void split1(float v, __nv_bfloat16& h, __nv_bfloat16& l) {
    h = __float2bfloat16(v);
    l = __float2bfloat16(v - __bfloat162float(h));
}

// stage layout constants (bytes): 64-row tiles, k-stage 64, 2 pipeline stages
#define MAT_B   (64 * PADK3 * 2)        // 9216
#define STAGE_B (4 * MAT_B)             // 36864
#define NSTAGE  2
#define TG_SMEM (NSTAGE * STAGE_B)      // 73728

// ================= tensor-core GEMM (bf16x3, k64, 2-stage cp.async) ========
__global__ __launch_bounds__(128, 3)
void tgemm(const __nv_bfloat16* __restrict__ Ahi, const __nv_bfloat16* __restrict__ Alo,
           const __nv_bfloat16* __restrict__ Bhi, const __nv_bfloat16* __restrict__ Blo,
           float* __restrict__ C,
           __nv_bfloat16* __restrict__ Chi, __nv_bfloat16* __restrict__ Clo,
           int M, int N, int K,
           const float* __restrict__ bias,
           const float* __restrict__ add_src,
           const float* __restrict__ probs,
           int flags, long sA, long sB, long sC, long sCh)
{
    extern __shared__ __align__(16) char dsmem[];
    const uint32_t ub = smem_to_u32(dsmem);

    const int tid = threadIdx.x;
    const int wid = tid >> 5;
    const int lane = tid & 31;
    const int warp_m = wid >> 1;
    const int warp_n = wid & 1;

    const int z = blockIdx.z;
    const __nv_bfloat16* Ah = Ahi + (size_t)z * sA;
    const __nv_bfloat16* Al = Alo + (size_t)z * sA;
    const __nv_bfloat16* Bh = Bhi + (size_t)z * sB;
    const __nv_bfloat16* Bl = Blo + (size_t)z * sB;
    const int bm = blockIdx.y * 64;
    const int bn = blockIdx.x * 64;

    float acc[2][4][4];
    #pragma unroll
    for (int i = 0; i < 2; i++)
        #pragma unroll
        for (int j = 0; j < 4; j++)
            #pragma unroll
            for (int q = 0; q < 4; q++) acc[i][j][q] = 0.0f;

    const int c0row = tid >> 3;
    const int c0kc  = (tid & 7) * 8;

    const uint32_t aoff = (uint32_t)((warp_m * 32 + (lane & 15)) * PADK3 + (lane >> 4) * 8) * 2;
    const uint32_t boff = (uint32_t)((warp_n * 32 + (lane & 7)) * PADK3 + ((lane >> 3) & 1) * 8) * 2;

    const int NKS = K >> 6;

    {
        const uint32_t sb = ub;
        #pragma unroll
        for (int it = 0; it < 4; it++) {
            const int row = c0row + it * 16;
            const uint32_t so = (uint32_t)(row * PADK3 + c0kc) * 2;
            const size_t ga = (size_t)(bm + row) * K + c0kc;
            const size_t gb = (size_t)(bn + row) * K + c0kc;
            cpasync16(sb + so, Ah + ga);
            cpasync16(sb + MAT_B + so, Al + ga);
            cpasync16(sb + 2 * MAT_B + so, Bh + gb);
            cpasync16(sb + 3 * MAT_B + so, Bl + gb);
        }
        asm volatile("cp.async.commit_group;");
    }

    for (int i = 0; i < NKS; i++) {
        asm volatile("cp.async.wait_group 0;");
        __syncthreads();

        if (i + 1 < NKS) {
            const uint32_t sb = ub + ((i + 1) & 1) * STAGE_B;
            const int k0 = (i + 1) << 6;
            #pragma unroll
            for (int it = 0; it < 4; it++) {
                const int row = c0row + it * 16;
                const uint32_t so = (uint32_t)(row * PADK3 + c0kc) * 2;
                const size_t ga = (size_t)(bm + row) * K + k0 + c0kc;
                const size_t gb = (size_t)(bn + row) * K + k0 + c0kc;
                cpasync16(sb + so, Ah + ga);
                cpasync16(sb + MAT_B + so, Al + ga);
                cpasync16(sb + 2 * MAT_B + so, Bh + gb);
                cpasync16(sb + 3 * MAT_B + so, Bl + gb);
            }
        }
        asm volatile("cp.async.commit_group;");

        const uint32_t sb = ub + (i & 1) * STAGE_B;
        #pragma unroll
        for (int ks = 0; ks < 4; ks++) {
            const uint32_t kb = (uint32_t)ks * 32;
            uint32_t ah[2][4], al[2][4];
            uint32_t bh[4][2], bl[4][2];
            #pragma unroll
            for (int mi = 0; mi < 2; mi++) {
                const uint32_t ao = sb + aoff + (uint32_t)(mi * 16 * PADK3) * 2 + kb;
                ldsm_x4(ah[mi], ao);
                ldsm_x4(al[mi], ao + MAT_B);
            }
            #pragma unroll
            for (int nj = 0; nj < 4; nj++) {
                const uint32_t bo = sb + 2 * MAT_B + boff + (uint32_t)(nj * 8 * PADK3) * 2 + kb;
                ldsm_x2(bh[nj], bo);
                ldsm_x2(bl[nj], bo + MAT_B);
            }
            #pragma unroll
            for (int nj = 0; nj < 4; nj++)
                #pragma unroll
                for (int mi = 0; mi < 2; mi++)
                    mma_bf16(acc[mi][nj], ah[mi], bh[nj]);
            #pragma unroll
            for (int nj = 0; nj < 4; nj++)
                #pragma unroll
                for (int mi = 0; mi < 2; mi++)
                    mma_bf16(acc[mi][nj], ah[mi], bl[nj]);
            #pragma unroll
            for (int nj = 0; nj < 4; nj++)
                #pragma unroll
                for (int mi = 0; mi < 2; mi++)
                    mma_bf16(acc[mi][nj], al[mi], bh[nj]);
        }
    }

    // epilogue
    float* Cp = C + (size_t)z * sC;
    __nv_bfloat16* Chp = Chi + (size_t)z * sCh;
    __nv_bfloat16* Clp = Clo + (size_t)z * sCh;
    #pragma unroll
    for (int mi = 0; mi < 2; mi++) {
        #pragma unroll
        for (int nj = 0; nj < 4; nj++) {
            const int m0 = bm + warp_m * 32 + mi * 16 + (lane >> 2);
            const int n0 = bn + warp_n * 32 + nj * 8 + (lane & 3) * 2;
            float v00 = acc[mi][nj][0], v01 = acc[mi][nj][1];
            float v10 = acc[mi][nj][2], v11 = acc[mi][nj][3];
            if (flags & F_BIAS) {
                const float2 bb = *(const float2*)&bias[n0];
                v00 += bb.x; v01 += bb.y; v10 += bb.x; v11 += bb.y;
            }
            if (flags & F_ADD) {
                const float2 r0 = *(const float2*)&add_src[(size_t)m0 * N + n0];
                const float2 r1 = *(const float2*)&add_src[(size_t)(m0 + 8) * N + n0];
                v00 += r0.x; v01 += r0.y; v10 += r1.x; v11 += r1.y;
            }
            if (flags & F_GELU) {
                v00 = gelu_tanh(v00); v01 = gelu_tanh(v01);
                v10 = gelu_tanh(v10); v11 = gelu_tanh(v11);
            }
            if (flags & F_SCALE) {
                const float s0 = probs[(size_t)m0 * 4 + z];
                const float s1 = probs[(size_t)(m0 + 8) * 4 + z];
                v00 *= s0; v01 *= s0; v10 *= s1; v11 *= s1;
            }
            if (flags & F_OUT) {
                #pragma unroll
                for (int rr = 0; rr < 2; rr++) {
                    const int m = m0 + rr * 8;
                    const int t = m >> 8, hp = (m >> 4) & 15, wp = m & 15;
                    const int c = n0 >> 8, py = (n0 >> 4) & 15, px = n0 & 15;
                    const size_t oi = (((size_t)(t * 4 + c) * 256) + hp * 16 + py) * 256
                                      + wp * 16 + px;
                    float2 o; o.x = (rr ? v10 : v00); o.y = (rr ? v11 : v01);
                    *(float2*)&Cp[oi] = o;
                }
            } else if (!(flags & F_NOC)) {
                float2 o0; o0.x = v00; o0.y = v01;
                float2 o1; o1.x = v10; o1.y = v11;
                *(float2*)&Cp[(size_t)m0 * N + n0] = o0;
                *(float2*)&Cp[(size_t)(m0 + 8) * N + n0] = o1;
            }
            if (flags & F_SPLIT) {
                __nv_bfloat16 h0, l0, h1, l1, h2, l2, h3, l3;
                split1(v00, h0, l0); split1(v01, h1, l1);
                split1(v10, h2, l2); split1(v11, h3, l3);
                *(__nv_bfloat162*)&Chp[(size_t)m0 * N + n0] = __halves2bfloat162(h0, h1);
                *(__nv_bfloat162*)&Clp[(size_t)m0 * N + n0] = __halves2bfloat162(l0, l1);
                *(__nv_bfloat162*)&Chp[(size_t)(m0 + 8) * N + n0] = __halves2bfloat162(h2, h3);
                *(__nv_bfloat162*)&Clp[(size_t)(m0 + 8) * N + n0] = __halves2bfloat162(l2, l3);
            }
        }
    }
}

// ================= producers emitting bf16 hi/lo directly =================
__global__ void patchify_split(const float* __restrict__ x,
                               __nv_bfloat16* __restrict__ hi,
                               __nv_bfloat16* __restrict__ lo)
{
    int idx = blockIdx.x * blockDim.x + threadIdx.x;
    if (idx >= TOK * 1024) return;
    int tok = idx >> 10, k = idx & 1023;
    int t = tok >> 8, hp = (tok >> 4) & 15, wp = tok & 15;
    int c = k >> 8, py = (k >> 4) & 15, px = k & 15;
    float v = x[(((size_t)(t * 4 + c) * 256) + hp * 16 + py) * 256 + wp * 16 + px];
    split1(v, hi[idx], lo[idx]);
}

// LayerNorm -> fp32 (optional) + hi/lo; optionally fused router probs
__global__ void ln_split(const float* __restrict__ X, float* __restrict__ Yf,
                         __nv_bfloat16* __restrict__ Yh, __nv_bfloat16* __restrict__ Yl,
                         const float* __restrict__ w, const float* __restrict__ b,
                         const float* __restrict__ Wr, float* __restrict__ probs)
{
    __shared__ float sh[256];
    __shared__ float4 sv[256];
    int tok = blockIdx.x, tid = threadIdx.x;
    const float* x = X + (size_t)tok * 512;
    float v1 = x[tid], v2 = x[tid + 256];
    sh[tid] = v1 + v2;
    __syncthreads();
    for (int s = 128; s > 0; s >>= 1) { if (tid < s) sh[tid] += sh[tid + s]; __syncthreads(); }
    float mean = sh[0] * (1.0f / 512.0f);
    __syncthreads();
    float d1 = v1 - mean, d2 = v2 - mean;
    sh[tid] = d1 * d1 + d2 * d2;
    __syncthreads();
    for (int s = 128; s > 0; s >>= 1) { if (tid < s) sh[tid] += sh[tid + s]; __syncthreads(); }
    float rstd = rsqrtf(sh[0] * (1.0f / 512.0f) + 1e-5f);
    float y1 = d1 * rstd * w[tid] + b[tid];
    float y2 = d2 * rstd * w[tid + 256] + b[tid + 256];
    size_t o1 = (size_t)tok * 512 + tid, o2 = o1 + 256;
    if (Yf) { Yf[o1] = y1; Yf[o2] = y2; }
    split1(y1, Yh[o1], Yl[o1]);
    split1(y2, Yh[o2], Yl[o2]);
    if (Wr) {
        const float4 w1 = *(const float4*)&Wr[tid * 4];
        const float4 w2 = *(const float4*)&Wr[(tid + 256) * 4];
        float4 p;
        p.x = y1 * w1.x + y2 * w2.x;
        p.y = y1 * w1.y + y2 * w2.y;
        p.z = y1 * w1.z + y2 * w2.z;
        p.w = y1 * w1.w + y2 * w2.w;
        sv[tid] = p;
        __syncthreads();
        for (int s = 128; s > 0; s >>= 1) {
            if (tid < s) {
                sv[tid].x += sv[tid + s].x;
                sv[tid].y += sv[tid + s].y;
                sv[tid].z += sv[tid + s].z;
                sv[tid].w += sv[tid + s].w;
            }
            __syncthreads();
        }
        if (tid == 0) {
            float4 lg = sv[0];
            float mx = fmaxf(fmaxf(lg.x, lg.y), fmaxf(lg.z, lg.w));
            float e0 = expf(lg.x - mx), e1 = expf(lg.y - mx);
            float e2 = expf(lg.z - mx), e3 = expf(lg.w - mx);
            float inv = 1.0f / (e0 + e1 + e2 + e3);
            probs[tok * 4 + 0] = e0 * inv;
            probs[tok * 4 + 1] = e1 * inv;
            probs[tok * 4 + 2] = e2 * inv;
            probs[tok * 4 + 3] = e3 * inv;
        }
    }
}

__global__ void im2col_bf16(const __nv_bfloat16* __restrict__ znh,
                            const __nv_bfloat16* __restrict__ znl,
                            __nv_bfloat16* __restrict__ colh,
                            __nv_bfloat16* __restrict__ coll)
{
    int bid = blockIdx.x;
    int tok = bid / 9, pos = bid - tok * 9;
    int t = tok >> 8, hw = tok & 255;
    int y = hw >> 4, x = hw & 15;
    int ny = y + pos / 3 - 1, nx = x + pos % 3 - 1;
    int i = threadIdx.x;  // 0..63, each 8 bf16 (16B)
    uint4* dh = (uint4*)(colh + (size_t)tok * KCONV + pos * 512);
    uint4* dl = (uint4*)(coll + (size_t)tok * KCONV + pos * 512);
    if ((unsigned)ny < 16u && (unsigned)nx < 16u) {
        const size_t src = (size_t)(t * 256 + ny * 16 + nx) * 512;
        dh[i] = ((const uint4*)(znh + src))[i];
        dl[i] = ((const uint4*)(znl + src))[i];
    } else {
        uint4 zr = make_uint4(0, 0, 0, 0);
        dh[i] = zr;
        dl[i] = zr;
    }
}

__global__ void split_kernel(const float4* __restrict__ src,
                             __nv_bfloat162* __restrict__ hi,
                             __nv_bfloat162* __restrict__ lo, int n4)
{
    int i = blockIdx.x * blockDim.x + threadIdx.x;
    if (i >= n4) return;
    float4 v = src[i];
    __nv_bfloat16 h0, l0, h1, l1, h2, l2, h3, l3;
    split1(v.x, h0, l0); split1(v.y, h1, l1);
    split1(v.z, h2, l2); split1(v.w, h3, l3);
    hi[2 * i]     = __halves2bfloat162(h0, h1);
    hi[2 * i + 1] = __halves2bfloat162(h2, h3);
    lo[2 * i]     = __halves2bfloat162(l0, l1);
    lo[2 * i + 1] = __halves2bfloat162(l2, l3);
}

// tiled transpose+split: out[z][n*K+k] = src[z*sSrc + k*N + n]
__global__ void tsplit_kernel(const float* __restrict__ src,
                              __nv_bfloat16* __restrict__ hi,
                              __nv_bfloat16* __restrict__ lo,
                              int K, int N, long sSrc, long sDst)
{
    __shared__ float tile[32][33];
    const int kb = blockIdx.x * 32, nb = blockIdx.y * 32;
    const int z = blockIdx.z;
    const int tx = threadIdx.x, ty = threadIdx.y;
    const float* s = src + (size_t)z * sSrc;
    #pragma unroll
    for (int i = ty; i < 32; i += 8)
        tile[i][tx] = s[(size_t)(kb + i) * N + nb + tx];
    __syncthreads();
    __nv_bfloat16* hp = hi + (size_t)z * sDst;
    __nv_bfloat16* lp = lo + (size_t)z * sDst;
    #pragma unroll
    for (int i = ty; i < 32; i += 8) {
        const float v = tile[tx][i];
        __nv_bfloat16 h, l;
        split1(v, h, l);
        const size_t o = (size_t)(nb + i) * K + kb + tx;
        hp[o] = h;
        lp[o] = l;
    }
}

// tiled pack complex -> Bt[n][k] of 512x512 block matrix, split.
__global__ void pack_cplx_bt(const float* __restrict__ Re, const float* __restrict__ Im,
                             __nv_bfloat16* __restrict__ hi, __nv_bfloat16* __restrict__ lo)
{
    __shared__ float tile[32][33];
    const int kb = blockIdx.x * 32, nb = blockIdx.y * 32;
    const int tx = threadIdx.x, ty = threadIdx.y;
    const bool khi = kb >= 256, nhi = nb >= 256;
    const float* srcq = khi ? (nhi ? Re : Im) : (nhi ? Im : Re);
    const float sgn = (khi && !nhi) ? -1.0f : 1.0f;
    const int kq = kb - (khi ? 256 : 0), nq = nb - (nhi ? 256 : 0);
    #pragma unroll
    for (int i = ty; i < 32; i += 8)
        tile[i][tx] = sgn * srcq[(size_t)(kq + i) * 256 + nq + tx];
    __syncthreads();
    #pragma unroll
    for (int i = ty; i < 32; i += 8) {
        const float v = tile[tx][i];
        __nv_bfloat16 h, l;
        split1(v, h, l);
        const size_t o = (size_t)(nb + i) * 512 + kb + tx;
        hi[o] = h;
        lo[o] = l;
    }
}

// staged conv-weight pack: one CTA per oc
__global__ void conv_w_tsplit(const float* __restrict__ cw,
                              __nv_bfloat16* __restrict__ hi, __nv_bfloat16* __restrict__ lo)
{
    __shared__ __nv_bfloat16 sh[KCONV];
    __shared__ __nv_bfloat16 sl[KCONV];
    const int oc = blockIdx.x;
    const int tid = threadIdx.x;
    const float* s = cw + (size_t)oc * KCONV;
    for (int i = tid; i < KCONV; i += 256) {
        const int ic = i / 9, pos = i - ic * 9;
        __nv_bfloat16 h, l;
        split1(s[i], h, l);
        sh[pos * 512 + ic] = h;
        sl[pos * 512 + ic] = l;
    }
    __syncthreads();
    __nv_bfloat16* hp = hi + (size_t)oc * KCONV;
    __nv_bfloat16* lp = lo + (size_t)oc * KCONV;
    for (int i = tid; i < KCONV; i += 256) {
        hp[i] = sh[i];
        lp[i] = sl[i];
    }
}

// ================= elementwise / small kernels =================
__global__ void small_mm(const float* __restrict__ A, const float* __restrict__ B,
                         float* __restrict__ C, int M, int N, int K,
                         const float* __restrict__ bias, int act)
{
    int n = blockIdx.x * blockDim.x + threadIdx.x;
    int m = blockIdx.y;
    if (n >= N || m >= M) return;
    float acc = 0.0f;
    for (int k = 0; k < K; k++) acc += A[m * K + k] * B[k * N + n];
    if (bias) acc += bias[n];
    if (act == 1) acc = 1.0f / (1.0f + expf(-acc));
    C[m * N + n] = acc;
}

__global__ void pack_cplx_kernel(const float* __restrict__ Re, const float* __restrict__ Im,
                                 float* __restrict__ Bp)
{
    int idx = blockIdx.x * blockDim.x + threadIdx.x;
    if (idx >= 512 * 512) return;
    int k = idx >> 9, n = idx & 511;
    float v;
    if (k < 256) v = (n < 256) ? Re[k * 256 + n] : Im[k * 256 + (n - 256)];
    else {
        int d = k - 256;
        v = (n < 256) ? -Im[d * 256 + n] : Re[d * 256 + (n - 256)];
    }
    Bp[idx] = v;
}

// two-stage spatial mean: part[t][ch][c] = sum of 32 hw rows
__global__ void mean_part(const float* __restrict__ xe, float* __restrict__ part)
{
    int t = blockIdx.x, ch = blockIdx.y, c = threadIdx.x;
    float s = 0.0f;
    const int h0 = ch * 32;
    for (int hw = h0; hw < h0 + 32; hw++)
        s += xe[(size_t)((t << 8) + hw) * 512 + c];
    part[(size_t)(t * 8 + ch) * 512 + c] = s;
}
__global__ void mean_fin(const float* __restrict__ part, float* __restrict__ xm)
{
    int t = blockIdx.x, c = threadIdx.x;
    float s = 0.0f;
    #pragma unroll
    for (int ch = 0; ch < 8; ch++)
        s += part[(size_t)(t * 8 + ch) * 512 + c];
    xm[t * 512 + c] = s * (1.0f / 256.0f);
}

__global__ void scan_kernel(const float* __restrict__ xe, const float* __restrict__ gate,
                            const float* __restrict__ src,
                            const float* __restrict__ lam_re, const float* __restrict__ lam_im,
                            const float* __restrict__ dt,
                            const float2* __restrict__ hprev,
                            __nv_bfloat16* __restrict__ hh, __nv_bfloat16* __restrict__ hl,
                            float2* __restrict__ lasth)
{
    int e = threadIdx.x;
    int hw = blockIdx.x;
    float lr = lam_re[e], li = lam_im[e];
    float lamr = -(log1pf(expf(lr)) + 0.01f);
    float lami = li;
    float il2 = 1.0f / (lamr * lamr + lami * lami);
    float2 hp = hprev[hw * 256 + e];
    float hr = 0.0f, hi = 0.0f;
    float outr = 0.0f, outi = 0.0f;
    #pragma unroll
    for (int t = 0; t < TSTEPS; t++) {
        float d = dt[t];
        float ed = expf(lamr * d);
        float dr = ed * cosf(lami * d), di = ed * sinf(lami * d);
        float nr = dr - 1.0f;
        float ofr = (nr * lamr + di * lami) * il2;
        float ofi = (di * lamr - nr * lami) * il2;
        int tok = t * 256 + hw;
        float xr = xe[(size_t)tok * 512 + e], xi = xe[(size_t)tok * 512 + 256 + e];
        float g = gate[t * 256 + e];
        float sr = src[t * 512 + e], si = src[t * 512 + 256 + e];
        float fr = xr * g + sr * (1.0f - g);
        float fi = xi * g + si * (1.0f - g);
        float ur = fr * ofr - fi * ofi;
        float ui = fr * ofi + fi * ofr;
        float nhr = dr * hr - di * hi + ur;
        float nhi = dr * hi + di * hr + ui;
        hr = nhr; hi = nhi;
        outr = hr + (hp.x * dr - hp.y * di);
        outi = hi + (hp.x * di + hp.y * dr);
        size_t o1 = (size_t)tok * 512 + e, o2 = o1 + 256;
        split1(outr, hh[o1], hl[o1]);
        split1(outi, hh[o2], hl[o2]);
    }
    lasth[hw * 256 + e] = make_float2(outr, outi);
}

__global__ void reduce_moe_kernel(const float* __restrict__ x, const float* __restrict__ xn,
                                  const float* __restrict__ oexp, float* __restrict__ z)
{
    int i = blockIdx.x * blockDim.x + threadIdx.x;
    const int n4 = TOK * TWO_D / 4;
    if (i >= n4) return;
    const float4* x4  = (const float4*)x;
    const float4* xn4 = (const float4*)xn;
    const float4* o4  = (const float4*)oexp;
    float4 a = x4[i], b = xn4[i];
    float4 o0 = o4[i], o1 = o4[i + n4], o2 = o4[i + 2 * n4], o3 = o4[i + 3 * n4];
    float4 r;
    r.x = a.x + b.x + o0.x + o1.x + o2.x + o3.x;
    r.y = a.y + b.y + o0.y + o1.y + o2.y + o3.y;
    r.z = a.z + b.z + o0.z + o1.z + o2.z + o3.z;
    r.w = a.w + b.w + o0.w + o1.w + o2.w + o3.w;
    ((float4*)z)[i] = r;
}

__global__ void zero_f2_kernel(float2* p, int n)
{
    int i = blockIdx.x * blockDim.x + threadIdx.x;
    if (i < n) p[i] = make_float2(0.f, 0.f);
}

// ---------------- host orchestration ----------------
template <typename T, size_t N>
static T* sym_addr(const T (&sym)[N]) {
    void* p = nullptr;
    cudaGetSymbolAddress(&p, (const void*)&sym);
    return (T*)p;
}

extern "C" void kernel_launch(void* const* d_in, const int* in_sizes, int n_in,
                              void* d_out, int out_size)
{
    const float* x      = (const float*)d_in[0];
    const float* dt     = (const float*)d_in[1];
    const float* Wenc   = (const float*)d_in[2];
    const float* benc   = (const float*)d_in[3];
    const float* Wdec   = (const float*)d_in[4];
    const float* bdec   = (const float*)d_in[5];
    const float* ln_sp_w= (const float*)d_in[6];
    const float* ln_sp_b= (const float*)d_in[7];
    const float* conv_w = (const float*)d_in[8];
    const float* conv_b = (const float*)d_in[9];
    const float* E_re   = (const float*)d_in[10];
    const float* E_im   = (const float*)d_in[11];
    const float* Ed_re  = (const float*)d_in[12];
    const float* Ed_im  = (const float*)d_in[13];
    const float* Ws_re  = (const float*)d_in[14];
    const float* Ws_im  = (const float*)d_in[15];
    const float* Wg     = (const float*)d_in[16];
    const float* bg     = (const float*)d_in[17];
    const float* lam_re = (const float*)d_in[18];
    const float* lam_im = (const float*)d_in[19];
    const float* ln_t_w = (const float*)d_in[20];
    const float* ln_t_b = (const float*)d_in[21];
    const float* Wr     = (const float*)d_in[22];
    const float* W1     = (const float*)d_in[23];
    const float* W2     = (const float*)d_in[24];

    float*  p_z    = sym_addr(g_z);
    float*  p_x    = sym_addr(g_x);
    float*  p_xe   = sym_addr(g_xe);
    float*  p_xo   = sym_addr(g_xo);
    float*  p_xn   = sym_addr(g_xn);
    float*  p_oexp = sym_addr(g_oexp);
    float*  p_Bp   = sym_addr(g_Bp);
    float*  p_xm   = sym_addr(g_xm);
    float*  p_mp   = sym_addr(g_mpart);
    float*  p_gate = sym_addr(g_gate);
    float*  p_src  = sym_addr(g_src);
    float*  p_probs= sym_addr(g_probs);
    float2* p_hpA  = sym_addr(g_hpA);
    float2* p_hpB  = sym_addr(g_hpB);
    __nv_bfloat16* p_Ahi  = sym_addr(g_Ahi);
    __nv_bfloat16* p_Alo  = sym_addr(g_Alo);
    __nv_bfloat16* p_A2hi = sym_addr(g_A2hi);
    __nv_bfloat16* p_A2lo = sym_addr(g_A2lo);
    __nv_bfloat16* p_Bhi  = sym_addr(g_Bhi);
    __nv_bfloat16* p_Blo  = sym_addr(g_Blo);

    cudaFuncSetAttribute(tgemm, cudaFuncAttributeMaxDynamicSharedMemorySize, TG_SMEM);

    // zero h_prev for layer 0
    zero_f2_kernel<<<256, 256>>>(p_hpA, 256 * 256);

    // ---------------- encoder ----------------
    patchify_split<<<(TOK * 1024) / 256, 256>>>(x, p_Ahi, p_Alo);
    tsplit_kernel<<<dim3(1024 / 32, 512 / 32, 1), dim3(32, 8)>>>(
        Wenc, p_Bhi, p_Blo, 1024, 512, 0, 0);
    tgemm<<<dim3(8, 32, 1), 128, TG_SMEM>>>(p_Ahi, p_Alo, p_Bhi, p_Blo, p_z,
                                            p_A2hi, p_A2lo, TOK, 512, 1024,
                                            benc, nullptr, nullptr, F_BIAS, 0, 0, 0, 0);

    for (int l = 0; l < 2; l++) {
        const float* cE_re  = E_re  + l * 65536;
        const float* cE_im  = E_im  + l * 65536;
        const float* cEd_re = Ed_re + l * 65536;
        const float* cEd_im = Ed_im + l * 65536;
        const float* cWs_re = Ws_re + l * 65536;
        const float* cWs_im = Ws_im + l * 65536;

        // spatial LN -> zn hi/lo only
        ln_split<<<TOK, 256>>>(p_z, nullptr, p_A2hi, p_A2lo,
                               ln_sp_w + l * 512, ln_sp_b + l * 512, nullptr, nullptr);

        // conv: bf16 im2col + GEMM, epilogue = bias + residual, fp32 x + hi/lo x
        im2col_bf16<<<TOK * 9, 64>>>(p_A2hi, p_A2lo, p_Ahi, p_Alo);
        conv_w_tsplit<<<512, 256>>>(conv_w + (size_t)l * 512 * 512 * 9, p_Bhi, p_Blo);
        tgemm<<<dim3(8, 32, 1), 128, TG_SMEM>>>(p_Ahi, p_Alo, p_Bhi, p_Blo, p_x,
                                                p_A2hi, p_A2lo, TOK, 512, KCONV,
                                                conv_b + l * 512, p_z, nullptr,
                                                F_BIAS | F_ADD | F_SPLIT, 0, 0, 0, 0);

        // x_eigen = x @ E
        pack_cplx_bt<<<dim3(16, 16), dim3(32, 8)>>>(cE_re, cE_im, p_Bhi, p_Blo);
        tgemm<<<dim3(8, 32, 1), 128, TG_SMEM>>>(p_A2hi, p_A2lo, p_Bhi, p_Blo, p_xe,
                                                nullptr, nullptr, TOK, 512, 512,
                                                nullptr, nullptr, nullptr, 0, 0, 0, 0, 0);

        // spatial mean -> xm (two-stage)
        mean_part<<<dim3(8, 8), 512>>>(p_xe, p_mp);
        mean_fin<<<8, 512>>>(p_mp, p_xm);

        // source_seq = xm @ Ws, gate_seq = sigmoid(xm @ Wg + bg)  (tiny, fp32)
        pack_cplx_kernel<<<1024, 256>>>(cWs_re, cWs_im, p_Bp);
        small_mm<<<dim3(4, 8), 128>>>(p_xm, p_Bp, p_src, 8, 512, 512, nullptr, 0);
        small_mm<<<dim3(2, 8), 128>>>(p_xm, Wg + l * 512 * 256, p_gate, 8, 256, 512,
                                      bg + l * 256, 1);

        // temporal scan -> h hi/lo (GEMM A operand)
        float2* hp_in  = (l == 0) ? p_hpA : p_hpB;
        float2* hp_out = (l == 0) ? p_hpB : p_hpA;
        scan_kernel<<<256, 256>>>(p_xe, p_gate, p_src, lam_re + l * 256, lam_im + l * 256,
                                  dt, hp_in, p_A2hi, p_A2lo, hp_out);

        // x_out = h @ Ed
        pack_cplx_bt<<<dim3(16, 16), dim3(32, 8)>>>(cEd_re, cEd_im, p_Bhi, p_Blo);
        tgemm<<<dim3(8, 32, 1), 128, TG_SMEM>>>(p_A2hi, p_A2lo, p_Bhi, p_Blo, p_xo,
                                                nullptr, nullptr, TOK, 512, 512,
                                                nullptr, nullptr, nullptr, 0, 0, 0, 0, 0);

        // temporal LN -> xn fp32 + hi/lo + fused router probs
        ln_split<<<TOK, 256>>>(p_xo, p_xn, p_A2hi, p_A2lo,
                               ln_t_w + l * 512, ln_t_b + l * 512,
                               Wr + l * 512 * 4, p_probs);

        // MoE W1: hid[e] = gelu(xn @ W1[e]) -> hi/lo only, batched over experts
        tsplit_kernel<<<dim3(512 / 32, 1024 / 32, 4), dim3(32, 8)>>>(
            W1 + (size_t)l * 4 * 512 * 1024, p_Bhi, p_Blo, 512, 1024,
            (long)512 * 1024, (long)512 * 1024);
        tgemm<<<dim3(16, 32, 4), 128, TG_SMEM>>>(p_A2hi, p_A2lo, p_Bhi, p_Blo, nullptr,
                                                 p_Ahi, p_Alo, TOK, 1024, 512,
                                                 nullptr, nullptr, nullptr,
                                                 F_GELU | F_SPLIT | F_NOC,
                                                 0, (long)512 * 1024, 0, (long)TOK * 1024);

        // MoE W2: oexp[e] = probs[:,e] * (hid[e] @ W2[e])
        tsplit_kernel<<<dim3(1024 / 32, 512 / 32, 4), dim3(32, 8)>>>(
            W2 + (size_t)l * 4 * 1024 * 512, p_Bhi, p_Blo, 1024, 512,
            (long)1024 * 512, (long)1024 * 512);
        tgemm<<<dim3(8, 32, 4), 128, TG_SMEM>>>(p_Ahi, p_Alo, p_Bhi, p_Blo, p_oexp,
                                                nullptr, nullptr, TOK, 512, 1024,
                                                nullptr, nullptr, p_probs, F_SCALE,
                                                (long)TOK * 1024, (long)1024 * 512,
                                                (long)TOK * 512, 0);

        // z_next = x + xn + sum_e oexp[e]
        reduce_moe_kernel<<<(TOK * 512 / 4 + 255) / 256, 256>>>(p_x, p_xn, p_oexp, p_z);
    }

    // ---------------- decoder (fused unpatchify) ----------------
    split_kernel<<<(TOK * 512 / 4 + 255) / 256, 256>>>(
        (const float4*)p_z, (__nv_bfloat162*)p_A2hi, (__nv_bfloat162*)p_A2lo, TOK * 512 / 4);
    tsplit_kernel<<<dim3(512 / 32, 1024 / 32, 1), dim3(32, 8)>>>(
        Wdec, p_Bhi, p_Blo, 512, 1024, 0, 0);
    tgemm<<<dim3(16, 32, 1), 128, TG_SMEM>>>(p_A2hi, p_A2lo, p_Bhi, p_Blo, (float*)d_out,
                                             nullptr, nullptr, TOK, 1024, 512,
                                             bdec, nullptr, nullptr, F_BIAS | F_OUT,
                                             0, 0, 0, 0);
}